// round 1
// baseline (speedup 1.0000x reference)
#include <cuda_runtime.h>
#include <cuda_bf16.h>

// HDC token encoder:
//   out[b,i,d] = item_memory[token_ids[b,i], (d - i) mod D] / ||row||_2
// item_memory entries are exactly +/-1, so ||row||_2 == sqrt(D) == 100 exactly.
// => out = gathered, cyclically-rolled row * 0.01f. Pure memory-movement kernel.

#define B_ 8
#define S_ 2048
#define V_ 256
#define D_ 10000

__global__ __launch_bounds__(256, 8)
void hdc_encode_kernel(const int* __restrict__ token_ids,
                       const float* __restrict__ item_memory,
                       float* __restrict__ out)
{
    const int row = blockIdx.x;            // row = b*S + i, 0..B*S-1
    const int i   = row & (S_ - 1);        // S=2048 is a power of two
    const int tok = __ldg(&token_ids[row]);

    const float* __restrict__ src = item_memory + (long long)tok * D_;
    float4* __restrict__ dst = reinterpret_cast<float4*>(out + (long long)row * D_);

    // D/4 = 2500 float4 groups per row. Aligned vector stores, shifted scalar reads.
    #pragma unroll 2
    for (int g = threadIdx.x; g < D_ / 4; g += 256) {
        const int d = g << 2;

        int j0 = d + 0 - i; if (j0 < 0) j0 += D_;
        int j1 = d + 1 - i; if (j1 < 0) j1 += D_;
        int j2 = d + 2 - i; if (j2 < 0) j2 += D_;
        int j3 = d + 3 - i; if (j3 < 0) j3 += D_;

        float4 v;
        v.x = __ldg(&src[j0]) * 0.01f;
        v.y = __ldg(&src[j1]) * 0.01f;
        v.z = __ldg(&src[j2]) * 0.01f;
        v.w = __ldg(&src[j3]) * 0.01f;

        // Streaming store: output is never re-read; keep item_memory L2-resident.
        __stcs(&dst[g], v);
    }
}

extern "C" void kernel_launch(void* const* d_in, const int* in_sizes, int n_in,
                              void* d_out, int out_size)
{
    const int*   token_ids   = (const int*)  d_in[0];   // (B, S) int32
    const float* item_memory = (const float*)d_in[1];   // (V, D) float32
    float*       out         = (float*)d_out;           // (B, S, D) float32

    (void)in_sizes; (void)n_in; (void)out_size;

    hdc_encode_kernel<<<B_ * S_, 256>>>(token_ids, item_memory, out);
}

// round 2
// speedup vs baseline: 1.1806x; 1.1806x over previous
#include <cuda_runtime.h>
#include <cuda_bf16.h>

// HDC token encoder:
//   out[b,i,d] = item_memory[token_ids[b,i], (d - i) mod D] / ||row||_2
// item_memory entries are exactly +/-1, so ||row||_2 == sqrt(D) == 100 exactly.
// => out = gathered, cyclically-rolled row * 0.01f. Pure memory movement.
//
// R1 lesson: per-thread float4 assembly made warp-level loads lane-stride-16B
// (5 cache lines / load instr) and saturated L1TEX at 94%. This version keeps
// every warp memory instruction lane-consecutive:
//   load  src[d - i]  : consecutive, misaligned -> 2 wavefronts / 128B
//   store out[d]      : consecutive, aligned    -> 1 wavefront  / 128B

#define B_ 8
#define S_ 2048
#define V_ 256
#define D_ 10000

__global__ __launch_bounds__(256, 8)
void hdc_encode_kernel(const int* __restrict__ token_ids,
                       const float* __restrict__ item_memory,
                       float* __restrict__ out)
{
    const int row = blockIdx.x;            // row = b*S + i
    const int i   = row & (S_ - 1);        // S = 2048 (pow2)
    const int tok = __ldg(&token_ids[row]);

    const float* __restrict__ src = item_memory + (long long)tok * D_;
    float* __restrict__ dst = out + (long long)row * D_;

    // D = 10000 = 39*256 + 16. Main unrolled body covers 39 full strides,
    // tail handles the last 16 elements.
    int d = threadIdx.x;

    #pragma unroll 13
    for (int k = 0; k < 39; ++k, d += 256) {
        int j = d - i;                     // i < 2048 <= d_max, j in [-2047, 9983]
        if (j < 0) j += D_;
        __stcs(&dst[d], __ldg(&src[j]) * 0.01f);
    }

    if (d < D_) {                          // tail: threads 0..15
        int j = d - i;
        if (j < 0) j += D_;
        __stcs(&dst[d], __ldg(&src[j]) * 0.01f);
    }
}

extern "C" void kernel_launch(void* const* d_in, const int* in_sizes, int n_in,
                              void* d_out, int out_size)
{
    const int*   token_ids   = (const int*)  d_in[0];   // (B, S) int32
    const float* item_memory = (const float*)d_in[1];   // (V, D) float32
    float*       out         = (float*)d_out;           // (B, S, D) float32

    (void)in_sizes; (void)n_in; (void)out_size;

    hdc_encode_kernel<<<B_ * S_, 256>>>(token_ids, item_memory, out);
}